// round 10
// baseline (speedup 1.0000x reference)
#include <cuda_runtime.h>
#include <cuda_fp16.h>
#include <cstdint>

#define NPTS 32768
#define KNB  16

// Post-BN/ReLU features fp16, layout [b][n][o] (o contiguous). 8.4 MB, L2-resident.
__device__ __half g_Rh[2 * NPTS * 64];

#define SWZ(x) ((x) ^ (((x) >> 3) & 0x70))

__device__ __forceinline__ uint32_t smem_u32(const void* p) {
    uint32_t a;
    asm("{ .reg .u64 t; cvta.to.shared.u64 t, %1; cvt.u32.u64 %0, t; }" : "=r"(a) : "l"(p));
    return a;
}

#define LDSM4(r, addr) \
    asm volatile("ldmatrix.sync.aligned.m8n8.x4.shared.b16 {%0,%1,%2,%3}, [%4];" \
        : "=r"((r)[0]), "=r"((r)[1]), "=r"((r)[2]), "=r"((r)[3]) : "r"(addr))

#define MMA16816(d, a, b0, b1) \
    asm volatile("mma.sync.aligned.m16n8k16.row.col.f32.f16.f16.f32 " \
        "{%0,%1,%2,%3}, {%4,%5,%6,%7}, {%8,%9}, {%0,%1,%2,%3};" \
        : "+f"((d)[0]), "+f"((d)[1]), "+f"((d)[2]), "+f"((d)[3]) \
        : "r"((a)[0]), "r"((a)[1]), "r"((a)[2]), "r"((a)[3]), "r"(b0), "r"(b1))

// ---------------------------------------------------------------------------
// Stage 1 (HMMA): R[b][n][o] = relu( F[64n x 64c] @ Ws[64o x 64c]^T + bias )
// ---------------------------------------------------------------------------
__global__ __launch_bounds__(128) void spe_stage1(
    const float* __restrict__ feat,
    const float* __restrict__ W,
    const float* __restrict__ gamma,
    const float* __restrict__ beta,
    const float* __restrict__ rmean,
    const float* __restrict__ rvar)
{
    __shared__ __align__(128) char sA[64 * 128];   // F tile [n][c] fp16, SW128; reused for output
    __shared__ __align__(128) char sW[64 * 128];   // Ws [o][c] fp16, SW128
    __shared__ float sBias[64];

    const int tid = threadIdx.x, wid = tid >> 5, lane = tid & 31;
    const int b  = blockIdx.y;
    const int n0 = blockIdx.x * 64;

    if (tid < 64) {
        float inv = gamma[tid] * rsqrtf(rvar[tid] + 1e-5f);
        sBias[tid] = beta[tid] - rmean[tid] * inv;
    }

    #pragma unroll
    for (int e = tid; e < 2048; e += 128) {
        int o = e >> 5, c2 = e & 31;
        float inv = gamma[o] * rsqrtf(rvar[o] + 1e-5f);
        float2 w2 = *(const float2*)&W[o * 64 + c2 * 2];
        __half2 h = __floats2half2_rn(w2.x * inv, w2.y * inv);
        *(uint32_t*)(sW + SWZ(o * 128 + c2 * 4)) = *(uint32_t*)&h;
    }

    #pragma unroll
    for (int e = tid; e < 512; e += 128) {
        int c2 = e >> 4, nq = e & 15;   // c-pair, n-quad
        const float* p0 = &feat[((size_t)b * 64 + 2 * c2) * NPTS + n0 + nq * 4];
        float4 f0 = *(const float4*)p0;
        float4 f1 = *(const float4*)(p0 + NPTS);
        __half2 h0 = __floats2half2_rn(f0.x, f1.x);
        __half2 h1 = __floats2half2_rn(f0.y, f1.y);
        __half2 h2 = __floats2half2_rn(f0.z, f1.z);
        __half2 h3 = __floats2half2_rn(f0.w, f1.w);
        int nl = nq * 4;
        *(uint32_t*)(sA + SWZ((nl + 0) * 128 + c2 * 4)) = *(uint32_t*)&h0;
        *(uint32_t*)(sA + SWZ((nl + 1) * 128 + c2 * 4)) = *(uint32_t*)&h1;
        *(uint32_t*)(sA + SWZ((nl + 2) * 128 + c2 * 4)) = *(uint32_t*)&h2;
        *(uint32_t*)(sA + SWZ((nl + 3) * 128 + c2 * 4)) = *(uint32_t*)&h3;
    }
    __syncthreads();

    const uint32_t smA = smem_u32(sA), smW = smem_u32(sW);

    float acc[8][4];
    #pragma unroll
    for (int j = 0; j < 8; j++)
        #pragma unroll
        for (int q = 0; q < 4; q++) acc[j][q] = 0.f;

    int aBase;
    {
        int row_in = (lane & 7) + ((lane >> 3) & 1) * 8;
        int kchunk = ((lane >> 4) & 1) * 16;
        aBase = (wid * 16 + row_in) * 128 + kchunk;
    }
    int bBase[4];
    {
        int row_in = lane & 7;
        int nsel   = (lane >> 4) & 1;
        int kchunk = ((lane >> 3) & 1) * 16;
        #pragma unroll
        for (int jj = 0; jj < 4; jj++)
            bBase[jj] = ((2 * jj + nsel) * 8 + row_in) * 128 + kchunk;
    }

    #pragma unroll
    for (int k = 0; k < 4; k++) {
        uint32_t af[4], bf[4][4];
        LDSM4(af, smA + SWZ(aBase + k * 32));
        #pragma unroll
        for (int jj = 0; jj < 4; jj++)
            LDSM4(bf[jj], smW + SWZ(bBase[jj] + k * 32));
        #pragma unroll
        for (int j = 0; j < 8; j++)
            MMA16816(acc[j], af, bf[j >> 1][(j & 1) * 2], bf[j >> 1][(j & 1) * 2 + 1]);
    }

    __syncthreads();   // reuse sA for output staging

    const int r0 = wid * 16 + (lane >> 2);
    const int cq = lane & 3;
    #pragma unroll
    for (int j = 0; j < 8; j++) {
        float2 bb = *(float2*)&sBias[j * 8 + cq * 2];
        __half2 h01 = __floats2half2_rn(fmaxf(acc[j][0] + bb.x, 0.f),
                                        fmaxf(acc[j][1] + bb.y, 0.f));
        __half2 h23 = __floats2half2_rn(fmaxf(acc[j][2] + bb.x, 0.f),
                                        fmaxf(acc[j][3] + bb.y, 0.f));
        int colb = j * 16 + cq * 4;
        *(uint32_t*)(sA + SWZ(r0 * 128 + colb))       = *(uint32_t*)&h01;
        *(uint32_t*)(sA + SWZ((r0 + 8) * 128 + colb)) = *(uint32_t*)&h23;
    }
    __syncthreads();

    __half* Rb = g_Rh + (((size_t)b * NPTS + n0) << 6);
    #pragma unroll
    for (int i = tid; i < 512; i += 128) {
        int row = i >> 3, seg = i & 7;
        uint4 v = *(uint4*)(sA + SWZ(row * 128 + seg * 16));
        *(uint4*)(Rb + ((size_t)row << 6) + seg * 8) = v;
    }
}

// ---------------------------------------------------------------------------
// Stage 2: out[b][o][n] = R[b][n][o] + sum_k R[b][idx[n][k]][o]
// Block 128 threads = 16 points. Indices staged via smem (no redundant LDG).
// 8 threads/point, 16B uint4 gathers, fp16 HADD2 group trees, fp32 acc.
// ---------------------------------------------------------------------------
__device__ __forceinline__ void gred4(float* a, uint4 v0, uint4 v1, uint4 v2, uint4 v3) {
    #pragma unroll
    for (int j = 0; j < 4; j++) {
        __half2 s = __hadd2(__hadd2(((__half2*)&v0)[j], ((__half2*)&v1)[j]),
                            __hadd2(((__half2*)&v2)[j], ((__half2*)&v3)[j]));
        float2 f = __half22float2(s);
        a[2 * j]     += f.x;
        a[2 * j + 1] += f.y;
    }
}
__device__ __forceinline__ void acc16(float* a, uint4 v) {
    #pragma unroll
    for (int j = 0; j < 4; j++) {
        float2 f = __half22float2(((__half2*)&v)[j]);
        a[2 * j]     += f.x;
        a[2 * j + 1] += f.y;
    }
}

__global__ __launch_bounds__(128, 12) void spe_stage2(
    const int* __restrict__ nidx,
    float* __restrict__ out)
{
    __shared__ int   sIdx[16 * 16];
    __shared__ float s[16][68];

    const int b   = blockIdx.y;
    const int n0  = blockIdx.x * 16;
    const int tid = threadIdx.x;

    // Stage neighbor indices: 16 points x 16 idx, coalesced int4 by 64 threads
    if (tid < 64) {
        int p = tid >> 2, sg = tid & 3;
        int4 v = ((const int4*)(nidx + ((size_t)(b * NPTS + n0 + p)) * KNB))[sg];
        *(int4*)&sIdx[p * 16 + sg * 4] = v;
    }
    __syncthreads();

    const int p = tid >> 3;     // point 0..15
    const int g = tid & 7;      // 16B segment
    const int n = n0 + p;

    const __half* __restrict__ Rb = g_Rh + ((size_t)b << 21);
    const int* ip = &sIdx[p * 16];

    int4 i0 = *(const int4*)&ip[0];
    int4 i1 = *(const int4*)&ip[4];
    int4 i2 = *(const int4*)&ip[8];
    int4 i3 = *(const int4*)&ip[12];

    float a[8];
    #pragma unroll
    for (int j = 0; j < 8; j++) a[j] = 0.f;

    #define LD16(idx) (((const uint4*)(Rb + ((size_t)(idx) << 6)))[g])
    uint4 A0 = LD16(n);    uint4 A1 = LD16(i0.x); uint4 A2 = LD16(i0.y); uint4 A3 = LD16(i0.z);
    uint4 B0 = LD16(i0.w); uint4 B1 = LD16(i1.x); uint4 B2 = LD16(i1.y); uint4 B3 = LD16(i1.z);
    gred4(a, A0, A1, A2, A3);
    uint4 C0 = LD16(i1.w); uint4 C1 = LD16(i2.x); uint4 C2 = LD16(i2.y); uint4 C3 = LD16(i2.z);
    gred4(a, B0, B1, B2, B3);
    uint4 D0 = LD16(i2.w); uint4 D1 = LD16(i3.x); uint4 D2 = LD16(i3.y); uint4 D3 = LD16(i3.z);
    gred4(a, C0, C1, C2, C3);
    uint4 E0 = LD16(i3.w);
    gred4(a, D0, D1, D2, D3);
    acc16(a, E0);
    #undef LD16

    *(float4*)&s[p][g * 8]     = make_float4(a[0], a[1], a[2], a[3]);
    *(float4*)&s[p][g * 8 + 4] = make_float4(a[4], a[5], a[6], a[7]);
    __syncthreads();

    // coalesced write-out: out[b][o][n0..n0+15], 128 threads x 2 float4
    const int o = tid & 63;
    const int q = tid >> 6;    // 0..1
    #pragma unroll
    for (int h = 0; h < 2; h++) {
        int qq = q + h * 2;    // 0..3: chunk of 4 points
        float4 r;
        r.x = s[qq * 4 + 0][o];
        r.y = s[qq * 4 + 1][o];
        r.z = s[qq * 4 + 2][o];
        r.w = s[qq * 4 + 3][o];
        *(float4*)&out[((size_t)b * 64 + o) * NPTS + n0 + qq * 4] = r;
    }
}

extern "C" void kernel_launch(void* const* d_in, const int* in_sizes, int n_in,
                              void* d_out, int out_size) {
    const float* feature = (const float*)d_in[0];
    const int*   nidx    = (const int*)d_in[1];
    const float* W       = (const float*)d_in[2];
    const float* gamma   = (const float*)d_in[3];
    const float* beta    = (const float*)d_in[4];
    const float* rmean   = (const float*)d_in[5];
    const float* rvar    = (const float*)d_in[6];
    float* out = (float*)d_out;

    const int B = in_sizes[0] / (64 * NPTS);   // = 2

    dim3 g1(NPTS / 64, B);
    spe_stage1<<<g1, 128>>>(feature, W, gamma, beta, rmean, rvar);

    dim3 g2(NPTS / 16, B);
    spe_stage2<<<g2, 128>>>(nidx, out);
}

// round 11
// speedup vs baseline: 1.0012x; 1.0012x over previous
#include <cuda_runtime.h>
#include <cuda_fp16.h>
#include <cstdint>

#define NPTS 32768
#define KNB  16

// Post-BN/ReLU features fp16, layout [b][n][o] (o contiguous). 8.4 MB, L2-resident.
__device__ __half g_Rh[2 * NPTS * 64];

#define SWZ(x) ((x) ^ (((x) >> 3) & 0x70))

__device__ __forceinline__ uint32_t smem_u32(const void* p) {
    uint32_t a;
    asm("{ .reg .u64 t; cvta.to.shared.u64 t, %1; cvt.u32.u64 %0, t; }" : "=r"(a) : "l"(p));
    return a;
}

#define LDSM4(r, addr) \
    asm volatile("ldmatrix.sync.aligned.m8n8.x4.shared.b16 {%0,%1,%2,%3}, [%4];" \
        : "=r"((r)[0]), "=r"((r)[1]), "=r"((r)[2]), "=r"((r)[3]) : "r"(addr))

#define MMA16816(d, a, b0, b1) \
    asm volatile("mma.sync.aligned.m16n8k16.row.col.f32.f16.f16.f32 " \
        "{%0,%1,%2,%3}, {%4,%5,%6,%7}, {%8,%9}, {%0,%1,%2,%3};" \
        : "+f"((d)[0]), "+f"((d)[1]), "+f"((d)[2]), "+f"((d)[3]) \
        : "r"((a)[0]), "r"((a)[1]), "r"((a)[2]), "r"((a)[3]), "r"(b0), "r"(b1))

// ---------------------------------------------------------------------------
// Stage 1 (HMMA): R[b][n][o] = relu( F[128n x 64c] @ Ws[64o x 64c]^T + bias )
// 256 threads / 128-point tile, grid 512xB. rsqrtf computed ONCE per channel.
// ---------------------------------------------------------------------------
__global__ __launch_bounds__(256) void spe_stage1(
    const float* __restrict__ feat,
    const float* __restrict__ W,
    const float* __restrict__ gamma,
    const float* __restrict__ beta,
    const float* __restrict__ rmean,
    const float* __restrict__ rvar)
{
    __shared__ __align__(128) char sA[128 * 128];  // F tile [n][c] fp16, SW128; reused for output
    __shared__ __align__(128) char sW[64 * 128];   // Ws [o][c] fp16, SW128
    __shared__ float sInv[64];
    __shared__ float sBias[64];

    const int tid = threadIdx.x, wid = tid >> 5, lane = tid & 31;
    const int b  = blockIdx.y;
    const int n0 = blockIdx.x * 128;

    // Per-channel scale/bias: only 64 rsqrtf per CTA (was: per W element!)
    if (tid < 64) {
        float inv = gamma[tid] * rsqrtf(rvar[tid] + 1e-5f);
        sInv[tid]  = inv;
        sBias[tid] = beta[tid] - rmean[tid] * inv;
    }
    __syncthreads();

    // Ws[o][c] = W[o][c] * inv[o], fp16, rows of 128B (LDS for inv, no MUFU)
    #pragma unroll
    for (int e = tid; e < 2048; e += 256) {
        int o = e >> 5, c2 = e & 31;
        float inv = sInv[o];
        float2 w2 = *(const float2*)&W[o * 64 + c2 * 2];
        __half2 h = __floats2half2_rn(w2.x * inv, w2.y * inv);
        *(uint32_t*)(sW + SWZ(o * 128 + c2 * 4)) = *(uint32_t*)&h;
    }

    // F[n][c] fp16: transpose-convert from feat[b][c][n0..n0+127]
    #pragma unroll
    for (int e = tid; e < 1024; e += 256) {
        int c2 = e >> 5, nq = e & 31;   // c-pair, n-quad
        const float* p0 = &feat[((size_t)b * 64 + 2 * c2) * NPTS + n0 + nq * 4];
        float4 f0 = *(const float4*)p0;
        float4 f1 = *(const float4*)(p0 + NPTS);
        __half2 h0 = __floats2half2_rn(f0.x, f1.x);
        __half2 h1 = __floats2half2_rn(f0.y, f1.y);
        __half2 h2 = __floats2half2_rn(f0.z, f1.z);
        __half2 h3 = __floats2half2_rn(f0.w, f1.w);
        int nl = nq * 4;
        *(uint32_t*)(sA + SWZ((nl + 0) * 128 + c2 * 4)) = *(uint32_t*)&h0;
        *(uint32_t*)(sA + SWZ((nl + 1) * 128 + c2 * 4)) = *(uint32_t*)&h1;
        *(uint32_t*)(sA + SWZ((nl + 2) * 128 + c2 * 4)) = *(uint32_t*)&h2;
        *(uint32_t*)(sA + SWZ((nl + 3) * 128 + c2 * 4)) = *(uint32_t*)&h3;
    }
    __syncthreads();

    const uint32_t smA = smem_u32(sA), smW = smem_u32(sW);

    float acc[8][4];
    #pragma unroll
    for (int j = 0; j < 8; j++)
        #pragma unroll
        for (int q = 0; q < 4; q++) acc[j][q] = 0.f;

    // warp wid handles rows wid*16 .. wid*16+15 (8 warps x 16 = 128 rows)
    int aBase;
    {
        int row_in = (lane & 7) + ((lane >> 3) & 1) * 8;
        int kchunk = ((lane >> 4) & 1) * 16;
        aBase = (wid * 16 + row_in) * 128 + kchunk;
    }
    int bBase[4];
    {
        int row_in = lane & 7;
        int nsel   = (lane >> 4) & 1;
        int kchunk = ((lane >> 3) & 1) * 16;
        #pragma unroll
        for (int jj = 0; jj < 4; jj++)
            bBase[jj] = ((2 * jj + nsel) * 8 + row_in) * 128 + kchunk;
    }

    #pragma unroll
    for (int k = 0; k < 4; k++) {
        uint32_t af[4], bf[4][4];
        LDSM4(af, smA + SWZ(aBase + k * 32));
        #pragma unroll
        for (int jj = 0; jj < 4; jj++)
            LDSM4(bf[jj], smW + SWZ(bBase[jj] + k * 32));
        #pragma unroll
        for (int j = 0; j < 8; j++)
            MMA16816(acc[j], af, bf[j >> 1][(j & 1) * 2], bf[j >> 1][(j & 1) * 2 + 1]);
    }

    __syncthreads();   // reuse sA for output staging

    const int r0 = wid * 16 + (lane >> 2);
    const int cq = lane & 3;
    #pragma unroll
    for (int j = 0; j < 8; j++) {
        float2 bb = *(float2*)&sBias[j * 8 + cq * 2];
        __half2 h01 = __floats2half2_rn(fmaxf(acc[j][0] + bb.x, 0.f),
                                        fmaxf(acc[j][1] + bb.y, 0.f));
        __half2 h23 = __floats2half2_rn(fmaxf(acc[j][2] + bb.x, 0.f),
                                        fmaxf(acc[j][3] + bb.y, 0.f));
        int colb = j * 16 + cq * 4;
        *(uint32_t*)(sA + SWZ(r0 * 128 + colb))       = *(uint32_t*)&h01;
        *(uint32_t*)(sA + SWZ((r0 + 8) * 128 + colb)) = *(uint32_t*)&h23;
    }
    __syncthreads();

    // Coalesced copy-out: 128 rows x 128B
    __half* Rb = g_Rh + (((size_t)b * NPTS + n0) << 6);
    #pragma unroll
    for (int i = tid; i < 1024; i += 256) {
        int row = i >> 3, seg = i & 7;
        uint4 v = *(uint4*)(sA + SWZ(row * 128 + seg * 16));
        *(uint4*)(Rb + ((size_t)row << 6) + seg * 8) = v;
    }
}

// ---------------------------------------------------------------------------
// Stage 2 (R8 config, proven 17.1us): out[b][o][n] = R[b][n][o] + sum_k R[..idx..][o]
// 8 threads/point, 16B uint4 gathers, fp16 HADD2 group-of-4 trees, fp32 acc.
// Block 256 threads = 32 points, grid 2048.
// ---------------------------------------------------------------------------
__device__ __forceinline__ void gred4(float* a, uint4 v0, uint4 v1, uint4 v2, uint4 v3) {
    #pragma unroll
    for (int j = 0; j < 4; j++) {
        __half2 s = __hadd2(__hadd2(((__half2*)&v0)[j], ((__half2*)&v1)[j]),
                            __hadd2(((__half2*)&v2)[j], ((__half2*)&v3)[j]));
        float2 f = __half22float2(s);
        a[2 * j]     += f.x;
        a[2 * j + 1] += f.y;
    }
}
__device__ __forceinline__ void acc16(float* a, uint4 v) {
    #pragma unroll
    for (int j = 0; j < 4; j++) {
        float2 f = __half22float2(((__half2*)&v)[j]);
        a[2 * j]     += f.x;
        a[2 * j + 1] += f.y;
    }
}

__global__ __launch_bounds__(256) void spe_stage2(
    const int* __restrict__ nidx,
    float* __restrict__ out)
{
    __shared__ float s[32][68];

    const int b   = blockIdx.y;
    const int n0  = blockIdx.x * 32;
    const int tid = threadIdx.x;
    const int p   = tid >> 3;     // point 0..31
    const int g   = tid & 7;      // 16B segment
    const int n   = n0 + p;

    const __half* __restrict__ Rb = g_Rh + ((size_t)b << 21);

    const int4* ip = (const int4*)(nidx + ((size_t)(b * NPTS + n)) * KNB);
    int4 i0 = ip[0], i1 = ip[1], i2 = ip[2], i3 = ip[3];

    float a[8];
    #pragma unroll
    for (int j = 0; j < 8; j++) a[j] = 0.f;

    #define LD16(idx) (((const uint4*)(Rb + ((size_t)(idx) << 6)))[g])
    uint4 A0 = LD16(n);    uint4 A1 = LD16(i0.x); uint4 A2 = LD16(i0.y); uint4 A3 = LD16(i0.z);
    uint4 B0 = LD16(i0.w); uint4 B1 = LD16(i1.x); uint4 B2 = LD16(i1.y); uint4 B3 = LD16(i1.z);
    gred4(a, A0, A1, A2, A3);
    uint4 C0 = LD16(i1.w); uint4 C1 = LD16(i2.x); uint4 C2 = LD16(i2.y); uint4 C3 = LD16(i2.z);
    gred4(a, B0, B1, B2, B3);
    uint4 D0 = LD16(i2.w); uint4 D1 = LD16(i3.x); uint4 D2 = LD16(i3.y); uint4 D3 = LD16(i3.z);
    gred4(a, C0, C1, C2, C3);
    uint4 E0 = LD16(i3.w);
    gred4(a, D0, D1, D2, D3);
    acc16(a, E0);
    #undef LD16

    *(float4*)&s[p][g * 8]     = make_float4(a[0], a[1], a[2], a[3]);
    *(float4*)&s[p][g * 8 + 4] = make_float4(a[4], a[5], a[6], a[7]);
    __syncthreads();

    // coalesced write-out: out[b][o][n0..n0+31]
    const int o = tid & 63;
    const int q = tid >> 6;    // 0..3
    #pragma unroll
    for (int h = 0; h < 2; h++) {
        int qq = q + h * 4;    // 0..7
        float4 r;
        r.x = s[qq * 4 + 0][o];
        r.y = s[qq * 4 + 1][o];
        r.z = s[qq * 4 + 2][o];
        r.w = s[qq * 4 + 3][o];
        *(float4*)&out[((size_t)b * 64 + o) * NPTS + n0 + qq * 4] = r;
    }
}

extern "C" void kernel_launch(void* const* d_in, const int* in_sizes, int n_in,
                              void* d_out, int out_size) {
    const float* feature = (const float*)d_in[0];
    const int*   nidx    = (const int*)d_in[1];
    const float* W       = (const float*)d_in[2];
    const float* gamma   = (const float*)d_in[3];
    const float* beta    = (const float*)d_in[4];
    const float* rmean   = (const float*)d_in[5];
    const float* rvar    = (const float*)d_in[6];
    float* out = (float*)d_out;

    const int B = in_sizes[0] / (64 * NPTS);   // = 2

    dim3 g1(NPTS / 128, B);
    spe_stage1<<<g1, 256>>>(feature, W, gamma, beta, rmean, rvar);

    dim3 g2(NPTS / 32, B);
    spe_stage2<<<g2, 256>>>(nidx, out);
}

// round 14
// speedup vs baseline: 1.0817x; 1.0805x over previous
#include <cuda_runtime.h>
#include <cuda_fp16.h>
#include <cstdint>

#define NPTS 32768
#define KNB  16

// Post-BN/ReLU features fp16, layout [b][n][o] (o contiguous). 8.4 MB, L2-resident.
__device__ __half g_Rh[2 * NPTS * 64];

#define SWZ(x) ((x) ^ (((x) >> 3) & 0x70))

__device__ __forceinline__ uint32_t smem_u32(const void* p) {
    uint32_t a;
    asm("{ .reg .u64 t; cvta.to.shared.u64 t, %1; cvt.u32.u64 %0, t; }" : "=r"(a) : "l"(p));
    return a;
}

#define LDSM4(r, addr) \
    asm volatile("ldmatrix.sync.aligned.m8n8.x4.shared.b16 {%0,%1,%2,%3}, [%4];" \
        : "=r"((r)[0]), "=r"((r)[1]), "=r"((r)[2]), "=r"((r)[3]) : "r"(addr))

#define MMA16816(d, a, b0, b1) \
    asm volatile("mma.sync.aligned.m16n8k16.row.col.f32.f16.f16.f32 " \
        "{%0,%1,%2,%3}, {%4,%5,%6,%7}, {%8,%9}, {%0,%1,%2,%3};" \
        : "+f"((d)[0]), "+f"((d)[1]), "+f"((d)[2]), "+f"((d)[3]) \
        : "r"((a)[0]), "r"((a)[1]), "r"((a)[2]), "r"((a)[3]), "r"(b0), "r"(b1))

// ---------------------------------------------------------------------------
// Stage 1 (HMMA): R[b][n][o] = relu( F[64n x 64c] @ Ws[64o x 64c]^T + bias )
// R7 geometry (64-pt tile, 128 thr, 1024 CTAs) + rsqrtf-once-per-channel fix.
// ---------------------------------------------------------------------------
__global__ __launch_bounds__(128) void spe_stage1(
    const float* __restrict__ feat,
    const float* __restrict__ W,
    const float* __restrict__ gamma,
    const float* __restrict__ beta,
    const float* __restrict__ rmean,
    const float* __restrict__ rvar)
{
    __shared__ __align__(128) char sA[64 * 128];   // F tile [n][c] fp16, SW128; reused for output
    __shared__ __align__(128) char sW[64 * 128];   // Ws [o][c] fp16, SW128
    __shared__ float sInv[64];
    __shared__ float sBias[64];

    const int tid = threadIdx.x, wid = tid >> 5, lane = tid & 31;
    const int b  = blockIdx.y;
    const int n0 = blockIdx.x * 64;

    // 64 rsqrtf per CTA total (MUFU fix)
    if (tid < 64) {
        float inv = gamma[tid] * rsqrtf(rvar[tid] + 1e-5f);
        sInv[tid]  = inv;
        sBias[tid] = beta[tid] - rmean[tid] * inv;
    }
    __syncthreads();

    // Ws[o][c] = W[o][c] * inv[o], fp16, rows of 128B
    #pragma unroll
    for (int e = tid; e < 2048; e += 128) {
        int o = e >> 5, c2 = e & 31;
        float inv = sInv[o];
        float2 w2 = *(const float2*)&W[o * 64 + c2 * 2];
        __half2 h = __floats2half2_rn(w2.x * inv, w2.y * inv);
        *(uint32_t*)(sW + SWZ(o * 128 + c2 * 4)) = *(uint32_t*)&h;
    }

    // F[n][c] fp16: transpose-convert from feat[b][c][n0..n0+63]
    #pragma unroll
    for (int e = tid; e < 512; e += 128) {
        int c2 = e >> 4, nq = e & 15;   // c-pair, n-quad
        const float* p0 = &feat[((size_t)b * 64 + 2 * c2) * NPTS + n0 + nq * 4];
        float4 f0 = *(const float4*)p0;
        float4 f1 = *(const float4*)(p0 + NPTS);
        __half2 h0 = __floats2half2_rn(f0.x, f1.x);
        __half2 h1 = __floats2half2_rn(f0.y, f1.y);
        __half2 h2 = __floats2half2_rn(f0.z, f1.z);
        __half2 h3 = __floats2half2_rn(f0.w, f1.w);
        int nl = nq * 4;
        *(uint32_t*)(sA + SWZ((nl + 0) * 128 + c2 * 4)) = *(uint32_t*)&h0;
        *(uint32_t*)(sA + SWZ((nl + 1) * 128 + c2 * 4)) = *(uint32_t*)&h1;
        *(uint32_t*)(sA + SWZ((nl + 2) * 128 + c2 * 4)) = *(uint32_t*)&h2;
        *(uint32_t*)(sA + SWZ((nl + 3) * 128 + c2 * 4)) = *(uint32_t*)&h3;
    }
    __syncthreads();

    const uint32_t smA = smem_u32(sA), smW = smem_u32(sW);

    float acc[8][4];
    #pragma unroll
    for (int j = 0; j < 8; j++)
        #pragma unroll
        for (int q = 0; q < 4; q++) acc[j][q] = 0.f;

    int aBase;
    {
        int row_in = (lane & 7) + ((lane >> 3) & 1) * 8;
        int kchunk = ((lane >> 4) & 1) * 16;
        aBase = (wid * 16 + row_in) * 128 + kchunk;
    }
    int bBase[4];
    {
        int row_in = lane & 7;
        int nsel   = (lane >> 4) & 1;
        int kchunk = ((lane >> 3) & 1) * 16;
        #pragma unroll
        for (int jj = 0; jj < 4; jj++)
            bBase[jj] = ((2 * jj + nsel) * 8 + row_in) * 128 + kchunk;
    }

    #pragma unroll
    for (int k = 0; k < 4; k++) {
        uint32_t af[4], bf[4][4];
        LDSM4(af, smA + SWZ(aBase + k * 32));
        #pragma unroll
        for (int jj = 0; jj < 4; jj++)
            LDSM4(bf[jj], smW + SWZ(bBase[jj] + k * 32));
        #pragma unroll
        for (int j = 0; j < 8; j++)
            MMA16816(acc[j], af, bf[j >> 1][(j & 1) * 2], bf[j >> 1][(j & 1) * 2 + 1]);
    }

    __syncthreads();   // reuse sA for output staging

    const int r0 = wid * 16 + (lane >> 2);
    const int cq = lane & 3;
    #pragma unroll
    for (int j = 0; j < 8; j++) {
        float2 bb = *(float2*)&sBias[j * 8 + cq * 2];
        __half2 h01 = __floats2half2_rn(fmaxf(acc[j][0] + bb.x, 0.f),
                                        fmaxf(acc[j][1] + bb.y, 0.f));
        __half2 h23 = __floats2half2_rn(fmaxf(acc[j][2] + bb.x, 0.f),
                                        fmaxf(acc[j][3] + bb.y, 0.f));
        int colb = j * 16 + cq * 4;
        *(uint32_t*)(sA + SWZ(r0 * 128 + colb))       = *(uint32_t*)&h01;
        *(uint32_t*)(sA + SWZ((r0 + 8) * 128 + colb)) = *(uint32_t*)&h23;
    }
    __syncthreads();

    __half* Rb = g_Rh + (((size_t)b * NPTS + n0) << 6);
    #pragma unroll
    for (int i = tid; i < 512; i += 128) {
        int row = i >> 3, seg = i & 7;
        uint4 v = *(uint4*)(sA + SWZ(row * 128 + seg * 16));
        *(uint4*)(Rb + ((size_t)row << 6) + seg * 8) = v;
    }
}

// ---------------------------------------------------------------------------
// Stage 2 (R8 exact, proven 17.0us): out[b][o][n] = R[b][n][o] + sum_k R[..idx..][o]
// 8 threads/point, 16B uint4 gathers, fp16 HADD2 group-of-4 trees, fp32 acc.
// Block 256 threads = 32 points, grid 2048.
// ---------------------------------------------------------------------------
__device__ __forceinline__ void gred4(float* a, uint4 v0, uint4 v1, uint4 v2, uint4 v3) {
    #pragma unroll
    for (int j = 0; j < 4; j++) {
        __half2 s = __hadd2(__hadd2(((__half2*)&v0)[j], ((__half2*)&v1)[j]),
                            __hadd2(((__half2*)&v2)[j], ((__half2*)&v3)[j]));
        float2 f = __half22float2(s);
        a[2 * j]     += f.x;
        a[2 * j + 1] += f.y;
    }
}
__device__ __forceinline__ void acc16(float* a, uint4 v) {
    #pragma unroll
    for (int j = 0; j < 4; j++) {
        float2 f = __half22float2(((__half2*)&v)[j]);
        a[2 * j]     += f.x;
        a[2 * j + 1] += f.y;
    }
}

__global__ __launch_bounds__(256) void spe_stage2(
    const int* __restrict__ nidx,
    float* __restrict__ out)
{
    __shared__ float s[32][68];

    const int b   = blockIdx.y;
    const int n0  = blockIdx.x * 32;
    const int tid = threadIdx.x;
    const int p   = tid >> 3;     // point 0..31
    const int g   = tid & 7;      // 16B segment
    const int n   = n0 + p;

    const __half* __restrict__ Rb = g_Rh + ((size_t)b << 21);

    const int4* ip = (const int4*)(nidx + ((size_t)(b * NPTS + n)) * KNB);
    int4 i0 = ip[0], i1 = ip[1], i2 = ip[2], i3 = ip[3];

    float a[8];
    #pragma unroll
    for (int j = 0; j < 8; j++) a[j] = 0.f;

    #define LD16(idx) (((const uint4*)(Rb + ((size_t)(idx) << 6)))[g])
    uint4 A0 = LD16(n);    uint4 A1 = LD16(i0.x); uint4 A2 = LD16(i0.y); uint4 A3 = LD16(i0.z);
    uint4 B0 = LD16(i0.w); uint4 B1 = LD16(i1.x); uint4 B2 = LD16(i1.y); uint4 B3 = LD16(i1.z);
    gred4(a, A0, A1, A2, A3);
    uint4 C0 = LD16(i1.w); uint4 C1 = LD16(i2.x); uint4 C2 = LD16(i2.y); uint4 C3 = LD16(i2.z);
    gred4(a, B0, B1, B2, B3);
    uint4 D0 = LD16(i2.w); uint4 D1 = LD16(i3.x); uint4 D2 = LD16(i3.y); uint4 D3 = LD16(i3.z);
    gred4(a, C0, C1, C2, C3);
    uint4 E0 = LD16(i3.w);
    gred4(a, D0, D1, D2, D3);
    acc16(a, E0);
    #undef LD16

    *(float4*)&s[p][g * 8]     = make_float4(a[0], a[1], a[2], a[3]);
    *(float4*)&s[p][g * 8 + 4] = make_float4(a[4], a[5], a[6], a[7]);
    __syncthreads();

    // coalesced write-out: out[b][o][n0..n0+31]
    const int o = tid & 63;
    const int q = tid >> 6;    // 0..3
    #pragma unroll
    for (int h = 0; h < 2; h++) {
        int qq = q + h * 4;    // 0..7
        float4 r;
        r.x = s[qq * 4 + 0][o];
        r.y = s[qq * 4 + 1][o];
        r.z = s[qq * 4 + 2][o];
        r.w = s[qq * 4 + 3][o];
        *(float4*)&out[((size_t)b * 64 + o) * NPTS + n0 + qq * 4] = r;
    }
}

extern "C" void kernel_launch(void* const* d_in, const int* in_sizes, int n_in,
                              void* d_out, int out_size) {
    const float* feature = (const float*)d_in[0];
    const int*   nidx    = (const int*)d_in[1];
    const float* W       = (const float*)d_in[2];
    const float* gamma   = (const float*)d_in[3];
    const float* beta    = (const float*)d_in[4];
    const float* rmean   = (const float*)d_in[5];
    const float* rvar    = (const float*)d_in[6];
    float* out = (float*)d_out;

    const int B = in_sizes[0] / (64 * NPTS);   // = 2

    dim3 g1(NPTS / 64, B);
    spe_stage1<<<g1, 128>>>(feature, W, gamma, beta, rmean, rvar);

    dim3 g2(NPTS / 32, B);
    spe_stage2<<<g2, 256>>>(nidx, out);
}